// round 6
// baseline (speedup 1.0000x reference)
#include <cuda_runtime.h>
#include <cuda_fp16.h>

#define S 160
#define SS (S*S)
#define S3 (S*S*S)
#define DG 96
#define DG2 (DG*DG)
#define DG3 (DG*DG*DG)
#define IMG_H 240
#define IMG_W 320
#define NVIEW 3
#define NPIX (NVIEW*IMG_H*IMG_W)   // 230400
#define NSTEP 64
#define CLAMP_HI 158.999f          // f32(160 - 1.001)
#define NBLK 900

// packed resized SDF, half precision:
//   g_sdfh[(x*S+y)*S+z] = float2 whose bits are two __half2:
//     .x bits = (S[y][z], S[y][z+1])   .y bits = (S[y+1][z], S[y+1][z+1])
__device__ float2 g_sdfh[S3];      // 32 MB
__device__ float  g_tbuf[NPIX];    // final ray parameter t
__device__ float  g_psum[NBLK];
__device__ int    g_pcnt[NBLK];
__device__ int    g_count;         // zero-initialized; reset after use

union HF { __half2 h; float f; };

// ---------------------------------------------------------------------------
// Kernel 1: separable SDF resize 96^3 -> 160^3 (minus TRUNC), packed half4.
// ---------------------------------------------------------------------------
__global__ __launch_bounds__(160) void resize_sdf_kernel(const float* __restrict__ sdf) {
    int b = blockIdx.x;            // S*S
    int i = b / S, j = b % S;
    int j2 = min(j + 1, S - 1);
    int t = threadIdx.x;           // 160

    float cx = (i * 95.0f) / 159.0f;
    int x0 = (int)cx; float fx = cx - (float)x0; int x1 = min(x0 + 1, DG - 1);

    __shared__ float ls0[96], ls1[96];
    __shared__ float rA[161], rB[161];

    if (t < 96) {
        int xs = (x1 - x0) * DG2;
        float gxf = 1.0f - fx;
        {
            float cy = (j * 95.0f) / 159.0f;
            int y0 = (int)cy; float fy = cy - (float)y0; int y1 = min(y0 + 1, DG - 1);
            int base = (x0 * DG + y0) * DG + t;
            int ys = (y1 - y0) * DG;
            float gyf = 1.0f - fy;
            ls0[t] = __ldg(sdf + base) * (gxf * gyf) + __ldg(sdf + base + ys) * (gxf * fy)
                   + __ldg(sdf + base + xs) * (fx * gyf) + __ldg(sdf + base + xs + ys) * (fx * fy);
        }
        {
            float cy = (j2 * 95.0f) / 159.0f;
            int y0 = (int)cy; float fy = cy - (float)y0; int y1 = min(y0 + 1, DG - 1);
            int base = (x0 * DG + y0) * DG + t;
            int ys = (y1 - y0) * DG;
            float gyf = 1.0f - fy;
            ls1[t] = __ldg(sdf + base) * (gxf * gyf) + __ldg(sdf + base + ys) * (gxf * fy)
                   + __ldg(sdf + base + xs) * (fx * gyf) + __ldg(sdf + base + xs + ys) * (fx * fy);
        }
    }
    __syncthreads();

    float czf = (t * 95.0f) / 159.0f;
    int z0 = (int)czf; float fz = czf - (float)z0; int z1 = min(z0 + 1, DG - 1);

    float vA = fmaf(fz, ls0[z1] - ls0[z0], ls0[z0]) - 1.5f;
    float vB = fmaf(fz, ls1[z1] - ls1[z0], ls1[z0]) - 1.5f;
    rA[t] = vA; rB[t] = vB;
    if (t == 159) { rA[160] = vA; rB[160] = vB; }
    __syncthreads();

    HF lo, hi;
    lo.h = __floats2half2_rn(rA[t], rA[t + 1]);
    hi.h = __floats2half2_rn(rB[t], rB[t + 1]);
    g_sdfh[(i * S + j) * S + t] = make_float2(lo.f, hi.f);
}

// ---------------------------------------------------------------------------
// shared ray setup
// ---------------------------------------------------------------------------
__device__ __forceinline__ void ray_setup(const float* __restrict__ poses,
                                          int v, int w, int h,
                                          float& ox, float& oy, float& oz,
                                          float& dx, float& dy, float& dz) {
    const float offx[3] = {0.0f, 36.0f, 40.0f};
    const float offz[3] = {0.0f, 44.0f, 23.0f};
    const float* M = poses + v * 16;
    ox = M[3]  / 0.0301f + offx[v];
    oy = M[7]  / 0.0301f;
    oz = M[11] / 0.0301f + offz[v];
    float uu = ((float)w - 160.0f) / 277.0f;
    float vv = ((float)h - 120.0f) / 277.0f;
    dx = M[0] * uu + M[1] * vv + M[2];
    dy = M[4] * uu + M[5] * vv + M[6];
    dz = M[8] * uu + M[9] * vv + M[10];
    float nrm = sqrtf(dx * dx + dy * dy + dz * dz);
    dx /= nrm; dy /= nrm; dz /= nrm;
}

// ---------------------------------------------------------------------------
// Kernel 2: ray march on half grid -> write t. 2x 8B loads per step.
// grid (10, 30, 3), block 256, 8x4 warp tiles
// ---------------------------------------------------------------------------
__global__ __launch_bounds__(256, 6) void march_kernel(
        const float* __restrict__ poses) {
    int tid = threadIdx.x;
    int warp = tid >> 5, lane = tid & 31;
    int wx = warp & 3, wy = warp >> 2;
    int lx = lane & 7, ly = lane >> 3;
    int w = blockIdx.x * 32 + wx * 8 + lx;
    int h = blockIdx.y * 8 + wy * 4 + ly;
    int v = blockIdx.z;

    float ox, oy, oz, dx, dy, dz;
    ray_setup(poses, v, w, h, ox, oy, oz, dx, dy, dz);

    float t = 0.0f;
    bool alive = true;
#pragma unroll 1
    for (int it = 0; it < NSTEP; ++it) {
        if (alive) {
            float px = fmaf(t, dx, ox);
            float py = fmaf(t, dy, oy);
            float pz = fmaf(t, dz, oz);
            bool dead = (px < 0.0f && dx <= 0.0f) || (px > 159.0f && dx >= 0.0f)
                     || (py < 0.0f && dy <= 0.0f) || (py > 159.0f && dy >= 0.0f)
                     || (pz < 0.0f && dz <= 0.0f) || (pz > 159.0f && dz >= 0.0f);
            if (dead) {
                alive = false;
            } else {
                float cx = fminf(fmaxf(px, 0.0f), CLAMP_HI);
                float cy = fminf(fmaxf(py, 0.0f), CLAMP_HI);
                float cz = fminf(fmaxf(pz, 0.0f), CLAMP_HI);
                int x0 = (int)cx, y0 = (int)cy, z0 = (int)cz;
                float fx = cx - (float)x0, fy = cy - (float)y0, fz = cz - (float)z0;
                const float2* p = g_sdfh + ((x0 * S + y0) * S + z0);
                float2 A = __ldg(p);
                float2 B = __ldg(p + SS);
                HF u;
                u.f = A.x; float2 al = __half22float2(u.h);
                u.f = A.y; float2 ah = __half22float2(u.h);
                u.f = B.x; float2 bl = __half22float2(u.h);
                u.f = B.y; float2 bh = __half22float2(u.h);
                float a0 = fmaf(fz, al.y - al.x, al.x);
                float a1 = fmaf(fz, ah.y - ah.x, ah.x);
                float b0 = fmaf(fz, bl.y - bl.x, bl.x);
                float b1 = fmaf(fz, bh.y - bh.x, bh.x);
                float va = fmaf(fy, a1 - a0, a0);
                float vb = fmaf(fy, b1 - b0, b0);
                float s = fmaf(fx, vb - va, va);
                t = fmaf(fmaxf(s, 0.25f), 2.0f, t);
            }
        }
        if (__all_sync(0xffffffffu, !alive)) break;
    }

    g_tbuf[(v * IMG_H + h) * IMG_W + w] = t;
}

// 3-level separable weights for resized-trilerp-of-source-trilerp along one axis
__device__ __forceinline__ void axis_w(int c0, float f, float* W, int* g) {
    float cc0 = (c0 * 95.0f) / 159.0f;
    int b0 = (int)cc0; float f0 = cc0 - (float)b0;
    float cc1 = ((c0 + 1) * 95.0f) / 159.0f;
    int b1 = (int)cc1; float f1 = cc1 - (float)b1;
    int l = b1 - b0;                    // 0 or 1
    float g0 = 1.0f - f;
    float wa = f * (1.0f - f1), wb = f * f1;
    W[0] = g0 * (1.0f - f0) + (l == 0 ? wa : 0.0f);
    W[1] = g0 * f0 + (l == 0 ? wb : wa);
    W[2] = (l == 0 ? 0.0f : wb);
    g[0] = b0;
    g[1] = min(b0 + 1, DG - 1);
    g[2] = min(b0 + 2, DG - 1);
}

__device__ __forceinline__ float gather27(const float* __restrict__ src,
                                          const int* gx, const int* gy, const int* gz,
                                          const float* Wx, const float* Wy, const float* Wz) {
    float acc = 0.0f;
#pragma unroll
    for (int ia = 0; ia < 3; ia++) {
        float accy = 0.0f;
#pragma unroll
        for (int ib = 0; ib < 3; ib++) {
            const float* rr = src + (gx[ia] * DG + gy[ib]) * DG;
            float accz = __ldg(rr + gz[0]) * Wz[0]
                       + __ldg(rr + gz[1]) * Wz[1]
                       + __ldg(rr + gz[2]) * Wz[2];
            accy = fmaf(Wy[ib], accz, accy);
        }
        acc = fmaf(Wx[ia], accy, acc);
    }
    return acc;
}

// ---------------------------------------------------------------------------
// Kernel 3: shade + loss. Exact fp32 sdf for the mask; fused reduce.
// ---------------------------------------------------------------------------
__global__ __launch_bounds__(256) void shade_kernel(
        const float* __restrict__ sdfsrc,
        const float* __restrict__ rgb,
        const float* __restrict__ sem,
        const float* __restrict__ poses,
        const float* __restrict__ views,
        float* __restrict__ out) {
    int tid = threadIdx.x;
    int pix = blockIdx.x * 256 + tid;
    int v = pix / (IMG_H * IMG_W);
    int r = pix % (IMG_H * IMG_W);
    int h = r / IMG_W;
    int w = r % IMG_W;

    float ox, oy, oz, dx, dy, dz;
    ray_setup(poses, v, w, h, ox, oy, oz, dx, dy, dz);

    float t = g_tbuf[pix];
    float px = fmaf(t, dx, ox);
    float py = fmaf(t, dy, oy);
    float pz = fmaf(t, dz, oz);

    float cx = fminf(fmaxf(px, 0.0f), CLAMP_HI);
    float cy = fminf(fmaxf(py, 0.0f), CLAMP_HI);
    float cz = fminf(fmaxf(pz, 0.0f), CLAMP_HI);
    int x0 = (int)cx, y0 = (int)cy, z0 = (int)cz;
    float fx = cx - (float)x0, fy = cy - (float)y0, fz = cz - (float)z0;

    float Wx[3], Wy[3], Wz[3];
    int gx[3], gy[3], gz[3];
    axis_w(x0, fx, Wx, gx);
    axis_w(y0, fy, Wy, gy);
    axis_w(z0, fz, Wz, gz);

    // exact fp32 resized-sdf value at pos (identical math class to color path)
    float s = gather27(sdfsrc, gx, gy, gz, Wx, Wy, Wz) - 1.5f;

    bool inside = (px >= 0.0f) && (px <= 159.0f)
               && (py >= 0.0f) && (py <= 159.0f)
               && (pz >= 0.0f) && (pz <= 159.0f);
    bool valid = inside && (fabsf(s) < 1.0f);

    float contrib = 0.0f;
    int cnt = 0;
    if (valid) {
        float c0 = gather27(rgb,           gx, gy, gz, Wx, Wy, Wz);
        float c1 = gather27(rgb + DG3,     gx, gy, gz, Wx, Wy, Wz);
        float c2 = gather27(rgb + 2 * DG3, gx, gy, gz, Wx, Wy, Wz);

        int nx0 = min((int)(x0 * 0.6f), DG - 1);
        int nx1 = min((int)((x0 + 1) * 0.6f), DG - 1);
        int ny0 = min((int)(y0 * 0.6f), DG - 1);
        int ny1 = min((int)((y0 + 1) * 0.6f), DG - 1);
        int nz0 = min((int)(z0 * 0.6f), DG - 1);
        int nz1 = min((int)((z0 + 1) * 0.6f), DG - 1);
        float gxf = 1.0f - fx, gyf = 1.0f - fy, gzf = 1.0f - fz;
        const float* s00 = sem + (nx0 * DG + ny0) * DG;
        const float* s01 = sem + (nx0 * DG + ny1) * DG;
        const float* s10 = sem + (nx1 * DG + ny0) * DG;
        const float* s11 = sem + (nx1 * DG + ny1) * DG;
        float wv = gxf * gyf * (gzf * __ldg(s00 + nz0) + fz * __ldg(s00 + nz1))
                 + gxf * fy  * (gzf * __ldg(s01 + nz0) + fz * __ldg(s01 + nz1))
                 + fx  * gyf * (gzf * __ldg(s10 + nz0) + fz * __ldg(s10 + nz1))
                 + fx  * fy  * (gzf * __ldg(s11 + nz0) + fz * __ldg(s11 + nz1));

        const float* vw = views + (size_t)pix * 3;
        contrib = (fabsf(c0 - vw[0]) + fabsf(c1 - vw[1]) + fabsf(c2 - vw[2])) * wv;
        cnt = 1;
    }

    __shared__ float ssum[256];
    __shared__ int scnt[256];
    ssum[tid] = contrib;
    scnt[tid] = cnt;
    __syncthreads();
#pragma unroll
    for (int o = 128; o > 0; o >>= 1) {
        if (tid < o) {
            ssum[tid] += ssum[tid + o];
            scnt[tid] += scnt[tid + o];
        }
        __syncthreads();
    }
    __shared__ bool amLast;
    if (tid == 0) {
        g_psum[blockIdx.x] = ssum[0];
        g_pcnt[blockIdx.x] = scnt[0];
        __threadfence();
        int tk = atomicAdd(&g_count, 1);
        amLast = (tk == NBLK - 1);
    }
    __syncthreads();

    if (amLast) {
        float sacc = 0.0f; int cacc = 0;
        for (int k = tid; k < NBLK; k += 256) {
            sacc += g_psum[k];
            cacc += g_pcnt[k];
        }
        ssum[tid] = sacc;
        scnt[tid] = cacc;
        __syncthreads();
#pragma unroll
        for (int o = 128; o > 0; o >>= 1) {
            if (tid < o) {
                ssum[tid] += ssum[tid + o];
                scnt[tid] += scnt[tid + o];
            }
            __syncthreads();
        }
        if (tid == 0) {
            float nv = 3.0f * (float)scnt[0];
            out[0] = 8.0f * ssum[0] / fmaxf(nv, 1.0f);
            g_count = 0;
        }
    }
}

// ---------------------------------------------------------------------------
extern "C" void kernel_launch(void* const* d_in, const int* in_sizes, int n_in,
                              void* d_out, int out_size) {
    const float* sdf   = (const float*)d_in[0];
    const float* rgb   = (const float*)d_in[1];
    const float* sem   = (const float*)d_in[2];
    const float* poses = (const float*)d_in[3];
    const float* views = (const float*)d_in[4];

    resize_sdf_kernel<<<S * S, 160>>>(sdf);
    dim3 mg(IMG_W / 32, IMG_H / 8, NVIEW);
    march_kernel<<<mg, 256>>>(poses);
    shade_kernel<<<NBLK, 256>>>(sdf, rgb, sem, poses, views, (float*)d_out);
}

// round 7
// speedup vs baseline: 1.0444x; 1.0444x over previous
#include <cuda_runtime.h>
#include <cuda_fp16.h>

#define S 160
#define SS (S*S)
#define S3 (S*S*S)
#define DG 96
#define DG2 (DG*DG)
#define DG3 (DG*DG*DG)
#define IMG_H 240
#define IMG_W 320
#define NVIEW 3
#define NSTEP 64
#define CLAMP_HI 158.999f          // f32(160 - 1.001)
#define NBLK 900

// packed resized SDF, half precision:
//   g_sdfh[(x*S+y)*S+z] = float2 whose bits are two __half2:
//     .x bits = (S[y][z], S[y][z+1])   .y bits = (S[y+1][z], S[y+1][z+1])
__device__ float2 g_sdfh[S3];      // 32 MB
__device__ float  g_psum[NBLK];
__device__ int    g_pcnt[NBLK];
__device__ int    g_count;         // zero-initialized; reset after use

union HF { __half2 h; float f; };

// ---------------------------------------------------------------------------
// Kernel 1: separable SDF resize 96^3 -> 160^3 (minus TRUNC), packed half4.
// Block = 192 threads: threads 0-95 build row j, 96-191 build row j+1.
// Stage 2 (threads 0-159) computes z / z+1 lerps directly (no smem round trip).
// ---------------------------------------------------------------------------
__global__ __launch_bounds__(192) void resize_sdf_kernel(const float* __restrict__ sdf) {
    int b = blockIdx.x;            // S*S
    int i = b / S, j = b % S;
    int t = threadIdx.x;           // 192

    float cx = (i * 95.0f) / 159.0f;
    int x0 = (int)cx; float fx = cx - (float)x0; int x1 = min(x0 + 1, DG - 1);

    __shared__ float ls[2][96];

    if (t < 192) {
        int row = t >= 96;                       // 0 -> j, 1 -> j+1
        int z = t - row * 96;                    // 0..95
        int jj = row ? min(j + 1, S - 1) : j;
        float cy = (jj * 95.0f) / 159.0f;
        int y0 = (int)cy; float fy = cy - (float)y0; int y1 = min(y0 + 1, DG - 1);
        int base = (x0 * DG + y0) * DG + z;
        int xs = (x1 - x0) * DG2;
        int ys = (y1 - y0) * DG;
        float gxf = 1.0f - fx, gyf = 1.0f - fy;
        ls[row][z] = __ldg(sdf + base) * (gxf * gyf) + __ldg(sdf + base + ys) * (gxf * fy)
                   + __ldg(sdf + base + xs) * (fx * gyf) + __ldg(sdf + base + xs + ys) * (fx * fy);
    }
    __syncthreads();

    if (t < S) {
        // z lerp at output z = t
        float czf = (t * 95.0f) / 159.0f;
        int z0 = (int)czf; float fz = czf - (float)z0; int z1 = min(z0 + 1, DG - 1);
        float vA0 = fmaf(fz, ls[0][z1] - ls[0][z0], ls[0][z0]) - 1.5f;
        float vB0 = fmaf(fz, ls[1][z1] - ls[1][z0], ls[1][z0]) - 1.5f;

        // z lerp at output z = t+1 (recomputed locally; t=159 value unused by march)
        int t1 = min(t + 1, S - 1);
        float czg = (t1 * 95.0f) / 159.0f;
        int w0 = (int)czg; float fw = czg - (float)w0; int w1 = min(w0 + 1, DG - 1);
        float vA1 = fmaf(fw, ls[0][w1] - ls[0][w0], ls[0][w0]) - 1.5f;
        float vB1 = fmaf(fw, ls[1][w1] - ls[1][w0], ls[1][w0]) - 1.5f;

        HF lo, hi;
        lo.h = __floats2half2_rn(vA0, vA1);
        hi.h = __floats2half2_rn(vB0, vB1);
        g_sdfh[(i * S + j) * S + t] = make_float2(lo.f, hi.f);
    }
}

// ---------------------------------------------------------------------------
// half4 SDF sample: 2x 8B loads, fp32 lerp
// ---------------------------------------------------------------------------
__device__ __forceinline__ float sdf_sample_h(int x0, int y0, int z0,
                                              float fx, float fy, float fz) {
    const float2* p = g_sdfh + ((x0 * S + y0) * S + z0);
    float2 A = __ldg(p);
    float2 B = __ldg(p + SS);
    HF u;
    u.f = A.x; float2 al = __half22float2(u.h);
    u.f = A.y; float2 ah = __half22float2(u.h);
    u.f = B.x; float2 bl = __half22float2(u.h);
    u.f = B.y; float2 bh = __half22float2(u.h);
    float a0 = fmaf(fz, al.y - al.x, al.x);
    float a1 = fmaf(fz, ah.y - ah.x, ah.x);
    float b0 = fmaf(fz, bl.y - bl.x, bl.x);
    float b1 = fmaf(fz, bh.y - bh.x, bh.x);
    float va = fmaf(fy, a1 - a0, a0);
    float vb = fmaf(fy, b1 - b0, b0);
    return fmaf(fx, vb - va, va);
}

// 3-level separable weights for resized-trilerp-of-source-trilerp along one axis
__device__ __forceinline__ void axis_w(int c0, float f, float* W, int* g) {
    float cc0 = (c0 * 95.0f) / 159.0f;
    int b0 = (int)cc0; float f0 = cc0 - (float)b0;
    float cc1 = ((c0 + 1) * 95.0f) / 159.0f;
    int b1 = (int)cc1; float f1 = cc1 - (float)b1;
    int l = b1 - b0;                    // 0 or 1
    float g0 = 1.0f - f;
    float wa = f * (1.0f - f1), wb = f * f1;
    W[0] = g0 * (1.0f - f0) + (l == 0 ? wa : 0.0f);
    W[1] = g0 * f0 + (l == 0 ? wb : wa);
    W[2] = (l == 0 ? 0.0f : wb);
    g[0] = b0;
    g[1] = min(b0 + 1, DG - 1);
    g[2] = min(b0 + 2, DG - 1);
}

__device__ __forceinline__ float gather27(const float* __restrict__ src,
                                          const int* gx, const int* gy, const int* gz,
                                          const float* Wx, const float* Wy, const float* Wz) {
    float acc = 0.0f;
#pragma unroll
    for (int ia = 0; ia < 3; ia++) {
        float accy = 0.0f;
#pragma unroll
        for (int ib = 0; ib < 3; ib++) {
            const float* rr = src + (gx[ia] * DG + gy[ib]) * DG;
            float accz = __ldg(rr + gz[0]) * Wz[0]
                       + __ldg(rr + gz[1]) * Wz[1]
                       + __ldg(rr + gz[2]) * Wz[2];
            accy = fmaf(Wy[ib], accz, accy);
        }
        acc = fmaf(Wx[ia], accy, acc);
    }
    return acc;
}

// ---------------------------------------------------------------------------
// Kernel 2: fused march + shade + loss. grid (10, 30, 3), block 256.
// ---------------------------------------------------------------------------
__global__ __launch_bounds__(256) void march_kernel(
        const float* __restrict__ rgb,
        const float* __restrict__ sem,
        const float* __restrict__ poses,
        const float* __restrict__ views,
        float* __restrict__ out) {
    int tid = threadIdx.x;
    int warp = tid >> 5, lane = tid & 31;
    int wx = warp & 3, wy = warp >> 2;
    int lx = lane & 7, ly = lane >> 3;
    int w = blockIdx.x * 32 + wx * 8 + lx;
    int h = blockIdx.y * 8 + wy * 4 + ly;
    int v = blockIdx.z;

    const float offx[3] = {0.0f, 36.0f, 40.0f};
    const float offz[3] = {0.0f, 44.0f, 23.0f};
    const float* M = poses + v * 16;
    float ox = M[3]  / 0.0301f + offx[v];
    float oy = M[7]  / 0.0301f;
    float oz = M[11] / 0.0301f + offz[v];
    float uu = ((float)w - 160.0f) / 277.0f;
    float vv = ((float)h - 120.0f) / 277.0f;
    float dx = M[0] * uu + M[1] * vv + M[2];
    float dy = M[4] * uu + M[5] * vv + M[6];
    float dz = M[8] * uu + M[9] * vv + M[10];
    float nrm = sqrtf(dx * dx + dy * dy + dz * dz);
    dx /= nrm; dy /= nrm; dz /= nrm;

    float t = 0.0f;
    bool alive = true;
#pragma unroll 1
    for (int it = 0; it < NSTEP; ++it) {
        if (alive) {
            float px = fmaf(t, dx, ox);
            float py = fmaf(t, dy, oy);
            float pz = fmaf(t, dz, oz);
            bool dead = (px < 0.0f && dx <= 0.0f) || (px > 159.0f && dx >= 0.0f)
                     || (py < 0.0f && dy <= 0.0f) || (py > 159.0f && dy >= 0.0f)
                     || (pz < 0.0f && dz <= 0.0f) || (pz > 159.0f && dz >= 0.0f);
            if (dead) {
                alive = false;
            } else {
                float cx = fminf(fmaxf(px, 0.0f), CLAMP_HI);
                float cy = fminf(fmaxf(py, 0.0f), CLAMP_HI);
                float cz = fminf(fmaxf(pz, 0.0f), CLAMP_HI);
                int x0 = (int)cx, y0 = (int)cy, z0 = (int)cz;
                float s = sdf_sample_h(x0, y0, z0,
                                       cx - (float)x0, cy - (float)y0, cz - (float)z0);
                t = fmaf(fmaxf(s, 0.25f), 2.0f, t);
            }
        }
        if (__all_sync(0xffffffffu, !alive)) break;
    }

    float contrib = 0.0f;
    int cnt = 0;
    if (alive) {
        float px = fmaf(t, dx, ox);
        float py = fmaf(t, dy, oy);
        float pz = fmaf(t, dz, oz);
        float cx = fminf(fmaxf(px, 0.0f), CLAMP_HI);
        float cy = fminf(fmaxf(py, 0.0f), CLAMP_HI);
        float cz = fminf(fmaxf(pz, 0.0f), CLAMP_HI);
        int x0 = (int)cx, y0 = (int)cy, z0 = (int)cz;
        float fx = cx - (float)x0, fy = cy - (float)y0, fz = cz - (float)z0;

        float s = sdf_sample_h(x0, y0, z0, fx, fy, fz);

        bool inside = (px >= 0.0f) && (px <= 159.0f)
                   && (py >= 0.0f) && (py <= 159.0f)
                   && (pz >= 0.0f) && (pz <= 159.0f);
        bool valid = inside && (fabsf(s) < 1.0f);

        if (valid) {
            float Wx[3], Wy[3], Wz[3];
            int gx[3], gy[3], gz[3];
            axis_w(x0, fx, Wx, gx);
            axis_w(y0, fy, Wy, gy);
            axis_w(z0, fz, Wz, gz);

            float c0 = gather27(rgb,           gx, gy, gz, Wx, Wy, Wz);
            float c1 = gather27(rgb + DG3,     gx, gy, gz, Wx, Wy, Wz);
            float c2 = gather27(rgb + 2 * DG3, gx, gy, gz, Wx, Wy, Wz);

            int nx0 = min((int)(x0 * 0.6f), DG - 1);
            int nx1 = min((int)((x0 + 1) * 0.6f), DG - 1);
            int ny0 = min((int)(y0 * 0.6f), DG - 1);
            int ny1 = min((int)((y0 + 1) * 0.6f), DG - 1);
            int nz0 = min((int)(z0 * 0.6f), DG - 1);
            int nz1 = min((int)((z0 + 1) * 0.6f), DG - 1);
            float gxf = 1.0f - fx, gyf = 1.0f - fy, gzf = 1.0f - fz;
            const float* s00 = sem + (nx0 * DG + ny0) * DG;
            const float* s01 = sem + (nx0 * DG + ny1) * DG;
            const float* s10 = sem + (nx1 * DG + ny0) * DG;
            const float* s11 = sem + (nx1 * DG + ny1) * DG;
            float wv = gxf * gyf * (gzf * __ldg(s00 + nz0) + fz * __ldg(s00 + nz1))
                     + gxf * fy  * (gzf * __ldg(s01 + nz0) + fz * __ldg(s01 + nz1))
                     + fx  * gyf * (gzf * __ldg(s10 + nz0) + fz * __ldg(s10 + nz1))
                     + fx  * fy  * (gzf * __ldg(s11 + nz0) + fz * __ldg(s11 + nz1));

            const float* vw = views + ((size_t)(v * IMG_H + h) * IMG_W + w) * 3;
            contrib = (fabsf(c0 - vw[0]) + fabsf(c1 - vw[1]) + fabsf(c2 - vw[2])) * wv;
            cnt = 1;
        }
    }

    // deterministic block reduction + last-block finish
    __shared__ float ssum[256];
    __shared__ int scnt[256];
    ssum[tid] = contrib;
    scnt[tid] = cnt;
    __syncthreads();
#pragma unroll
    for (int o = 128; o > 0; o >>= 1) {
        if (tid < o) {
            ssum[tid] += ssum[tid + o];
            scnt[tid] += scnt[tid + o];
        }
        __syncthreads();
    }
    int bid = (blockIdx.z * gridDim.y + blockIdx.y) * gridDim.x + blockIdx.x;
    __shared__ bool amLast;
    if (tid == 0) {
        g_psum[bid] = ssum[0];
        g_pcnt[bid] = scnt[0];
        __threadfence();
        int tk = atomicAdd(&g_count, 1);
        amLast = (tk == NBLK - 1);
    }
    __syncthreads();

    if (amLast) {
        float sacc = 0.0f; int cacc = 0;
        for (int k = tid; k < NBLK; k += 256) {
            sacc += g_psum[k];
            cacc += g_pcnt[k];
        }
        ssum[tid] = sacc;
        scnt[tid] = cacc;
        __syncthreads();
#pragma unroll
        for (int o = 128; o > 0; o >>= 1) {
            if (tid < o) {
                ssum[tid] += ssum[tid + o];
                scnt[tid] += scnt[tid + o];
            }
            __syncthreads();
        }
        if (tid == 0) {
            float nv = 3.0f * (float)scnt[0];
            out[0] = 8.0f * ssum[0] / fmaxf(nv, 1.0f);
            g_count = 0;
        }
    }
}

// ---------------------------------------------------------------------------
extern "C" void kernel_launch(void* const* d_in, const int* in_sizes, int n_in,
                              void* d_out, int out_size) {
    const float* sdf   = (const float*)d_in[0];
    const float* rgb   = (const float*)d_in[1];
    const float* sem   = (const float*)d_in[2];
    const float* poses = (const float*)d_in[3];
    const float* views = (const float*)d_in[4];

    resize_sdf_kernel<<<S * S, 192>>>(sdf);
    dim3 mg(IMG_W / 32, IMG_H / 8, NVIEW);
    march_kernel<<<mg, 256>>>(rgb, sem, poses, views, (float*)d_out);
}